// round 10
// baseline (speedup 1.0000x reference)
#include <cuda_runtime.h>
#include <cuda_bf16.h>
#include <math.h>
#include <stdint.h>

// Problem constants
#define Bb 4
#define Tt 512
#define Cc 1024
#define Hh 16
#define Ll 8
#define FSs 64
#define Vv 3
#define Dd 64          // head dim
#define Mrows (Bb*Tt)  // 2048

// ---------------------------------------------------------------------------
// Device-global scratch (no allocations allowed)
// ---------------------------------------------------------------------------
__device__ float g_x  [Mrows * Cc];
__device__ float g_h  [Mrows * Cc];
__device__ float g_qkv[Mrows * 3 * Cc];
__device__ float g_y  [Mrows * Cc];
__device__ float g_fc [Mrows * 4 * Cc];
// tf32-pre-rounded weights (same [L][K][N] layout as inputs)
__device__ float g_wR_attn [Ll * Cc * 3 * Cc];
__device__ float g_wR_attnp[Ll * Cc * Cc];
__device__ float g_wR_fc   [Ll * Cc * 4 * Cc];
__device__ float g_wR_proj [Ll * 4 * Cc * Cc];

// ---------------------------------------------------------------------------
// Helpers
// ---------------------------------------------------------------------------
__device__ __forceinline__ unsigned f2tf32(float x) {
    unsigned r;
    asm("cvt.rna.tf32.f32 %0, %1;" : "=r"(r) : "f"(x));
    return r;
}
__device__ __forceinline__ float tf32r(float x) { return __uint_as_float(f2tf32(x)); }

__device__ __forceinline__ uint32_t smem_u32(const void* p) {
    uint32_t a;
    asm("{ .reg .u64 t; cvta.to.shared.u64 t, %1; cvt.u32.u64 %0, t; }" : "=r"(a) : "l"(p));
    return a;
}
__device__ __forceinline__ void cp_async16(uint32_t dst, const void* src) {
    asm volatile("cp.async.cg.shared.global [%0], [%1], 16;" :: "r"(dst), "l"(src));
}
#define CP_COMMIT() asm volatile("cp.async.commit_group;" ::: "memory")
#define CP_WAIT(n)  asm volatile("cp.async.wait_group %0;" :: "n"(n) : "memory")

__device__ __forceinline__ void mma_tf32(float c[4], const unsigned a[4],
                                         unsigned b0, unsigned b1) {
    asm volatile(
        "mma.sync.aligned.m16n8k8.row.col.f32.tf32.tf32.f32 "
        "{%0,%1,%2,%3}, {%4,%5,%6,%7}, {%8,%9}, {%0,%1,%2,%3};"
        : "+f"(c[0]), "+f"(c[1]), "+f"(c[2]), "+f"(c[3])
        : "r"(a[0]), "r"(a[1]), "r"(a[2]), "r"(a[3]), "r"(b0), "r"(b1));
}

// ---------------------------------------------------------------------------
// Elementwise tf32 rounding of weights
// ---------------------------------------------------------------------------
__global__ void round_w(const float* __restrict__ in, float* __restrict__ out,
                        size_t n4)
{
    size_t stride = (size_t)gridDim.x * blockDim.x;
    for (size_t i = blockIdx.x * (size_t)blockDim.x + threadIdx.x; i < n4; i += stride) {
        float4 v = ((const float4*)in)[i];
        v.x = tf32r(v.x); v.y = tf32r(v.y); v.z = tf32r(v.z); v.w = tf32r(v.w);
        ((float4*)out)[i] = v;
    }
}

// ---------------------------------------------------------------------------
// TF32 tensor-core GEMM (mma.sync), cp.async 3-stage pipeline, BK=32.
// 128x128 tiles. FIX vs R7: CP_COMMIT is UNCONDITIONAL each iteration
// (empty groups at the tail) so CP_WAIT(1) always guarantees stage kt landed.
// ---------------------------------------------------------------------------
#define LDA 36
#define LDB 132
#define A_STG (128 * LDA)
#define B_STG (32 * LDB)
#define GEMM_SMEM ((3 * (A_STG + B_STG)) * 4)

template <bool RELU, bool RES, bool ROUND>
__global__ void __launch_bounds__(256, 2)
gemm_tc(const float* __restrict__ A, const float* __restrict__ Bw,
        const float* __restrict__ bias, const float* __restrict__ res,
        float* __restrict__ C, int N, int K)
{
    extern __shared__ float sm[];
    float* Asm = sm;
    float* Bsm = sm + 3 * A_STG;

    int tid = threadIdx.x;
    int lane = tid & 31;
    int warp = tid >> 5;
    int blockRow = blockIdx.y * 128;
    int blockCol = blockIdx.x * 128;

    const float* Abase = A  + (size_t)blockRow * K;
    const float* Bbase = Bw + blockCol;
    int nk = K / 32;

    // NOTE: no CP_COMMIT inside — caller commits (possibly empty) groups.
    auto load_stage = [&](int kt, int s) {
        float* as = Asm + s * A_STG;
        float* bs = Bsm + s * B_STG;
        #pragma unroll
        for (int i = 0; i < 4; i++) {
            int q = tid + i * 256;
            int r = q >> 3, c = q & 7;
            cp_async16(smem_u32(as + r * LDA + c * 4),
                       Abase + (size_t)r * K + kt * 32 + c * 4);
            int k = q >> 5, c2 = q & 31;
            cp_async16(smem_u32(bs + k * LDB + c2 * 4),
                       Bbase + (size_t)(kt * 32 + k) * N + c2 * 4);
        }
    };

    load_stage(0, 0); CP_COMMIT();
    load_stage(1, 1); CP_COMMIT();

    int m0 = (warp >> 1) * 32;
    int n0 = (warp & 1) * 64;
    int g  = lane >> 2;
    int tg = lane & 3;

    float acc[2][8][4];
    #pragma unroll
    for (int mt = 0; mt < 2; mt++)
        #pragma unroll
        for (int nt = 0; nt < 8; nt++)
            #pragma unroll
            for (int i = 0; i < 4; i++) acc[mt][nt][i] = 0.f;

    for (int kt = 0; kt < nk; kt++) {
        CP_WAIT(1);          // stage kt resident (invariant: 2 groups pending)
        __syncthreads();

        const float* as = Asm + (kt % 3) * A_STG;
        const float* bs = Bsm + (kt % 3) * B_STG;

        #pragma unroll
        for (int ks = 0; ks < 32; ks += 8) {
            unsigned af[2][4];
            #pragma unroll
            for (int mt = 0; mt < 2; mt++) {
                int m = m0 + mt * 16 + g;
                af[mt][0] = __float_as_uint(as[m * LDA + ks + tg]);
                af[mt][1] = __float_as_uint(as[(m + 8) * LDA + ks + tg]);
                af[mt][2] = __float_as_uint(as[m * LDA + ks + tg + 4]);
                af[mt][3] = __float_as_uint(as[(m + 8) * LDA + ks + tg + 4]);
            }
            #pragma unroll
            for (int nt = 0; nt < 8; nt++) {
                int n = n0 + nt * 8 + g;
                unsigned b0 = __float_as_uint(bs[(ks + tg) * LDB + n]);
                unsigned b1 = __float_as_uint(bs[(ks + tg + 4) * LDB + n]);
                mma_tf32(acc[0][nt], af[0], b0, b1);
                mma_tf32(acc[1][nt], af[1], b0, b1);
            }
        }

        if (kt + 2 < nk) load_stage(kt + 2, (kt + 2) % 3);
        CP_COMMIT();         // unconditional: keeps group-count invariant
    }

    #pragma unroll
    for (int mt = 0; mt < 2; mt++) {
        #pragma unroll
        for (int nt = 0; nt < 8; nt++) {
            int col = blockCol + n0 + nt * 8 + tg * 2;
            size_t r0 = blockRow + m0 + mt * 16 + g;
            size_t r1 = r0 + 8;
            float b0v = bias[col], b1v = bias[col + 1];
            float2 o0 = make_float2(acc[mt][nt][0] + b0v, acc[mt][nt][1] + b1v);
            float2 o1 = make_float2(acc[mt][nt][2] + b0v, acc[mt][nt][3] + b1v);
            if (RES) {
                float2 rv0 = *(const float2*)(res + r0 * N + col);
                float2 rv1 = *(const float2*)(res + r1 * N + col);
                o0.x += rv0.x; o0.y += rv0.y;
                o1.x += rv1.x; o1.y += rv1.y;
            }
            if (RELU) {
                o0.x = fmaxf(o0.x, 0.f); o0.y = fmaxf(o0.y, 0.f);
                o1.x = fmaxf(o1.x, 0.f); o1.y = fmaxf(o1.y, 0.f);
            }
            if (ROUND) {
                o0.x = tf32r(o0.x); o0.y = tf32r(o0.y);
                o1.x = tf32r(o1.x); o1.y = tf32r(o1.y);
            }
            *(float2*)(C + r0 * N + col) = o0;
            *(float2*)(C + r1 * N + col) = o1;
        }
    }
}

// ---------------------------------------------------------------------------
// 64x128 tile variant for N=1024 GEMMs (attnp/proj): 256 CTAs instead of 128.
// Same fragment math / accumulation order; same tail-safe commit pattern.
// ---------------------------------------------------------------------------
#define A64_STG (64 * LDA)
#define GEMM64_SMEM ((3 * (A64_STG + B_STG)) * 4)

template <bool RELU, bool RES, bool ROUND>
__global__ void __launch_bounds__(256, 2)
gemm_tc64(const float* __restrict__ A, const float* __restrict__ Bw,
          const float* __restrict__ bias, const float* __restrict__ res,
          float* __restrict__ C, int N, int K)
{
    extern __shared__ float sm[];
    float* Asm = sm;
    float* Bsm = sm + 3 * A64_STG;

    int tid = threadIdx.x;
    int lane = tid & 31;
    int warp = tid >> 5;
    int blockRow = blockIdx.y * 64;
    int blockCol = blockIdx.x * 128;

    const float* Abase = A  + (size_t)blockRow * K;
    const float* Bbase = Bw + blockCol;
    int nk = K / 32;

    auto load_stage = [&](int kt, int s) {
        float* as = Asm + s * A64_STG;
        float* bs = Bsm + s * B_STG;
        #pragma unroll
        for (int i = 0; i < 2; i++) {
            int q = tid + i * 256;
            int r = q >> 3, c = q & 7;
            cp_async16(smem_u32(as + r * LDA + c * 4),
                       Abase + (size_t)r * K + kt * 32 + c * 4);
        }
        #pragma unroll
        for (int i = 0; i < 4; i++) {
            int q = tid + i * 256;
            int k = q >> 5, c2 = q & 31;
            cp_async16(smem_u32(bs + k * LDB + c2 * 4),
                       Bbase + (size_t)(kt * 32 + k) * N + c2 * 4);
        }
    };

    load_stage(0, 0); CP_COMMIT();
    load_stage(1, 1); CP_COMMIT();

    int m0 = (warp >> 2) * 32;       // 0 or 32
    int n0 = (warp & 3) * 32;        // 0,32,64,96
    int g  = lane >> 2;
    int tg = lane & 3;

    float acc[2][4][4];
    #pragma unroll
    for (int mt = 0; mt < 2; mt++)
        #pragma unroll
        for (int nt = 0; nt < 4; nt++)
            #pragma unroll
            for (int i = 0; i < 4; i++) acc[mt][nt][i] = 0.f;

    for (int kt = 0; kt < nk; kt++) {
        CP_WAIT(1);
        __syncthreads();

        const float* as = Asm + (kt % 3) * A64_STG;
        const float* bs = Bsm + (kt % 3) * B_STG;

        #pragma unroll
        for (int ks = 0; ks < 32; ks += 8) {
            unsigned af[2][4];
            #pragma unroll
            for (int mt = 0; mt < 2; mt++) {
                int m = m0 + mt * 16 + g;
                af[mt][0] = __float_as_uint(as[m * LDA + ks + tg]);
                af[mt][1] = __float_as_uint(as[(m + 8) * LDA + ks + tg]);
                af[mt][2] = __float_as_uint(as[m * LDA + ks + tg + 4]);
                af[mt][3] = __float_as_uint(as[(m + 8) * LDA + ks + tg + 4]);
            }
            #pragma unroll
            for (int nt = 0; nt < 4; nt++) {
                int n = n0 + nt * 8 + g;
                unsigned b0 = __float_as_uint(bs[(ks + tg) * LDB + n]);
                unsigned b1 = __float_as_uint(bs[(ks + tg + 4) * LDB + n]);
                mma_tf32(acc[0][nt], af[0], b0, b1);
                mma_tf32(acc[1][nt], af[1], b0, b1);
            }
        }

        if (kt + 2 < nk) load_stage(kt + 2, (kt + 2) % 3);
        CP_COMMIT();         // unconditional: keeps group-count invariant
    }

    #pragma unroll
    for (int mt = 0; mt < 2; mt++) {
        #pragma unroll
        for (int nt = 0; nt < 4; nt++) {
            int col = blockCol + n0 + nt * 8 + tg * 2;
            size_t r0 = blockRow + m0 + mt * 16 + g;
            size_t r1 = r0 + 8;
            float b0v = bias[col], b1v = bias[col + 1];
            float2 o0 = make_float2(acc[mt][nt][0] + b0v, acc[mt][nt][1] + b1v);
            float2 o1 = make_float2(acc[mt][nt][2] + b0v, acc[mt][nt][3] + b1v);
            if (RES) {
                float2 rv0 = *(const float2*)(res + r0 * N + col);
                float2 rv1 = *(const float2*)(res + r1 * N + col);
                o0.x += rv0.x; o0.y += rv0.y;
                o1.x += rv1.x; o1.y += rv1.y;
            }
            if (RELU) {
                o0.x = fmaxf(o0.x, 0.f); o0.y = fmaxf(o0.y, 0.f);
                o1.x = fmaxf(o1.x, 0.f); o1.y = fmaxf(o1.y, 0.f);
            }
            if (ROUND) {
                o0.x = tf32r(o0.x); o0.y = tf32r(o0.y);
                o1.x = tf32r(o1.x); o1.y = tf32r(o1.y);
            }
            *(float2*)(C + r0 * N + col) = o0;
            *(float2*)(C + r1 * N + col) = o1;
        }
    }
}

// ---------------------------------------------------------------------------
// Flash attention (tf32 mma) — unchanged from R7 (its unconditional
// CP_COMMIT already maintains the group-count invariant).
// ---------------------------------------------------------------------------
#define FLD 68
#define FA_TILE (64 * FLD)
#define FA_SMEM (4 * FA_TILE * 4)

__global__ void __launch_bounds__(128)
attn_fa(const float* __restrict__ qkv,
        const int* __restrict__ seq_ls,
        float* __restrict__ y)
{
    extern __shared__ float fsm[];
    float* Qs = fsm;
    float* Ks = Qs + FA_TILE;
    float* Vs = Ks + FA_TILE;
    float* Ps = Vs + FA_TILE;

    int tid  = threadIdx.x;
    int lane = tid & 31;
    int warp = tid >> 5;
    int g  = lane >> 2;
    int tg = lane & 3;
    int qb = blockIdx.x;
    int h  = blockIdx.y;
    int b  = blockIdx.z;
    int m0w = warp * 16;

    int lv = seq_ls[b];
    int ntiles = (lv + 63) >> 6;

    const float* qkv_b = qkv + (size_t)b * Tt * 3 * Cc;

    #pragma unroll
    for (int i = 0; i < 8; i++) {
        int q = i * 128 + tid;
        int r = q >> 4, c4 = q & 15;
        float4 v = *(const float4*)(qkv_b + (size_t)(qb * 64 + r) * 3 * Cc + h * Dd + c4 * 4);
        v.x = tf32r(v.x * 0.125f); v.y = tf32r(v.y * 0.125f);
        v.z = tf32r(v.z * 0.125f); v.w = tf32r(v.w * 0.125f);
        *(float4*)(Qs + r * FLD + c4 * 4) = v;
    }

    uint32_t Ks_u = smem_u32(Ks);
    uint32_t Vs_u = smem_u32(Vs);
    auto load_k = [&](int kt) {
        #pragma unroll
        for (int i = 0; i < 8; i++) {
            int q = i * 128 + tid;
            int r = q >> 4, c4 = q & 15;
            cp_async16(Ks_u + (r * FLD + c4 * 4) * 4,
                       qkv_b + (size_t)(kt * 64 + r) * 3 * Cc + Cc + h * Dd + c4 * 4);
        }
    };
    auto load_v = [&](int kt) {
        #pragma unroll
        for (int i = 0; i < 8; i++) {
            int q = i * 128 + tid;
            int r = q >> 4, c4 = q & 15;
            cp_async16(Vs_u + (r * FLD + c4 * 4) * 4,
                       qkv_b + (size_t)(kt * 64 + r) * 3 * Cc + 2 * Cc + h * Dd + c4 * 4);
        }
    };

    load_k(0); CP_COMMIT();
    load_v(0); CP_COMMIT();

    float m0 = -INFINITY, m1 = -INFINITY;
    float l0 = 0.f, l1 = 0.f;
    float oacc[8][4];
    #pragma unroll
    for (int nt = 0; nt < 8; nt++)
        #pragma unroll
        for (int i = 0; i < 4; i++) oacc[nt][i] = 0.f;

    for (int kt = 0; kt < ntiles; kt++) {
        int j0 = kt * 64;
        CP_WAIT(1);
        __syncthreads();

        float s[8][4];
        #pragma unroll
        for (int nt = 0; nt < 8; nt++)
            #pragma unroll
            for (int i = 0; i < 4; i++) s[nt][i] = 0.f;

        #pragma unroll
        for (int ks = 0; ks < 8; ks++) {
            unsigned af[4];
            af[0] = __float_as_uint(Qs[(m0w + g) * FLD + ks * 8 + tg]);
            af[1] = __float_as_uint(Qs[(m0w + g + 8) * FLD + ks * 8 + tg]);
            af[2] = __float_as_uint(Qs[(m0w + g) * FLD + ks * 8 + tg + 4]);
            af[3] = __float_as_uint(Qs[(m0w + g + 8) * FLD + ks * 8 + tg + 4]);
            #pragma unroll
            for (int nt = 0; nt < 8; nt++) {
                unsigned b0 = __float_as_uint(Ks[(nt * 8 + g) * FLD + ks * 8 + tg]);
                unsigned b1 = __float_as_uint(Ks[(nt * 8 + g) * FLD + ks * 8 + tg + 4]);
                mma_tf32(s[nt], af, b0, b1);
            }
        }

        __syncthreads();
        if (kt + 1 < ntiles) load_k(kt + 1);
        CP_COMMIT();

        float mx0 = -INFINITY, mx1 = -INFINITY;
        #pragma unroll
        for (int nt = 0; nt < 8; nt++) {
            int j = j0 + nt * 8 + 2 * tg;
            if (j >= lv)     { s[nt][0] = -INFINITY; s[nt][2] = -INFINITY; }
            if (j + 1 >= lv) { s[nt][1] = -INFINITY; s[nt][3] = -INFINITY; }
            mx0 = fmaxf(mx0, fmaxf(s[nt][0], s[nt][1]));
            mx1 = fmaxf(mx1, fmaxf(s[nt][2], s[nt][3]));
        }
        mx0 = fmaxf(mx0, __shfl_xor_sync(0xffffffffu, mx0, 1));
        mx0 = fmaxf(mx0, __shfl_xor_sync(0xffffffffu, mx0, 2));
        mx1 = fmaxf(mx1, __shfl_xor_sync(0xffffffffu, mx1, 1));
        mx1 = fmaxf(mx1, __shfl_xor_sync(0xffffffffu, mx1, 2));

        float mn0 = fmaxf(m0, mx0), mn1 = fmaxf(m1, mx1);
        float corr0 = __expf(m0 - mn0), corr1 = __expf(m1 - mn1);

        float sum0 = 0.f, sum1 = 0.f;
        #pragma unroll
        for (int nt = 0; nt < 8; nt++) {
            float p00 = __expf(s[nt][0] - mn0);
            float p01 = __expf(s[nt][1] - mn0);
            float p10 = __expf(s[nt][2] - mn1);
            float p11 = __expf(s[nt][3] - mn1);
            sum0 += p00 + p01;
            sum1 += p10 + p11;
            int colr = nt * 8 + 2 * tg;
            *(float2*)(Ps + (m0w + g) * FLD + colr) =
                make_float2(tf32r(p00), tf32r(p01));
            *(float2*)(Ps + (m0w + g + 8) * FLD + colr) =
                make_float2(tf32r(p10), tf32r(p11));
        }
        sum0 += __shfl_xor_sync(0xffffffffu, sum0, 1);
        sum0 += __shfl_xor_sync(0xffffffffu, sum0, 2);
        sum1 += __shfl_xor_sync(0xffffffffu, sum1, 1);
        sum1 += __shfl_xor_sync(0xffffffffu, sum1, 2);
        l0 = l0 * corr0 + sum0;
        l1 = l1 * corr1 + sum1;
        m0 = mn0; m1 = mn1;

        #pragma unroll
        for (int nt = 0; nt < 8; nt++) {
            oacc[nt][0] *= corr0; oacc[nt][1] *= corr0;
            oacc[nt][2] *= corr1; oacc[nt][3] *= corr1;
        }

        CP_WAIT(1);
        __syncthreads();

        #pragma unroll
        for (int ks = 0; ks < 8; ks++) {
            unsigned af[4];
            af[0] = __float_as_uint(Ps[(m0w + g) * FLD + ks * 8 + tg]);
            af[1] = __float_as_uint(Ps[(m0w + g + 8) * FLD + ks * 8 + tg]);
            af[2] = __float_as_uint(Ps[(m0w + g) * FLD + ks * 8 + tg + 4]);
            af[3] = __float_as_uint(Ps[(m0w + g + 8) * FLD + ks * 8 + tg + 4]);
            #pragma unroll
            for (int nt = 0; nt < 8; nt++) {
                unsigned b0 = __float_as_uint(Vs[(ks * 8 + tg) * FLD + nt * 8 + g]);
                unsigned b1 = __float_as_uint(Vs[(ks * 8 + tg + 4) * FLD + nt * 8 + g]);
                mma_tf32(oacc[nt], af, b0, b1);
            }
        }

        __syncthreads();
        if (kt + 1 < ntiles) load_v(kt + 1);
        CP_COMMIT();
    }

    float inv0 = 1.0f / l0, inv1 = 1.0f / l1;
    int t0 = qb * 64 + m0w + g;
    #pragma unroll
    for (int nt = 0; nt < 8; nt++) {
        int col = h * Dd + nt * 8 + 2 * tg;
        *(float2*)(y + (size_t)(b * Tt + t0) * Cc + col) =
            make_float2(tf32r(oacc[nt][0] * inv0), tf32r(oacc[nt][1] * inv0));
        *(float2*)(y + (size_t)(b * Tt + t0 + 8) * Cc + col) =
            make_float2(tf32r(oacc[nt][2] * inv1), tf32r(oacc[nt][3] * inv1));
    }
}

// ---------------------------------------------------------------------------
// Embedding
// ---------------------------------------------------------------------------
__global__ void embed_kernel(const float* __restrict__ seqs,
                             const float* __restrict__ wte_w,
                             const float* __restrict__ wte_b,
                             const float* __restrict__ wpe,
                             float* __restrict__ x)
{
    int m = blockIdx.x;
    int t = m % Tt;
    __shared__ float sf[FSs];
    if (threadIdx.x < FSs) sf[threadIdx.x] = seqs[m * FSs + threadIdx.x];
    __syncthreads();

    #pragma unroll
    for (int cc = 0; cc < 4; cc++) {
        int c = threadIdx.x + cc * 256;
        float acc = wte_b[c] + wpe[t * Cc + c];
        #pragma unroll 8
        for (int f = 0; f < FSs; f++)
            acc = fmaf(sf[f], wte_w[f * Cc + c], acc);
        x[m * Cc + c] = acc;
    }
}

// ---------------------------------------------------------------------------
// LayerNorm
// ---------------------------------------------------------------------------
__global__ void ln_kernel(const float* __restrict__ x,
                          const float* __restrict__ s,
                          const float* __restrict__ b,
                          float* __restrict__ out, int rnd)
{
    int row = blockIdx.x;
    int tid = threadIdx.x;
    const float* xr = x + (size_t)row * Cc;

    float4 v = *(const float4*)(xr + tid * 4);
    float sum = v.x + v.y + v.z + v.w;
    float sumsq = v.x*v.x + v.y*v.y + v.z*v.z + v.w*v.w;

    #pragma unroll
    for (int off = 16; off > 0; off >>= 1) {
        sum   += __shfl_xor_sync(0xffffffffu, sum, off);
        sumsq += __shfl_xor_sync(0xffffffffu, sumsq, off);
    }
    __shared__ float red1[8], red2[8];
    int wid = tid >> 5, lane = tid & 31;
    if (lane == 0) { red1[wid] = sum; red2[wid] = sumsq; }
    __syncthreads();
    if (wid == 0) {
        float s1 = red1[lane & 7], s2 = red2[lane & 7];
        #pragma unroll
        for (int off = 4; off > 0; off >>= 1) {
            s1 += __shfl_xor_sync(0xffffffffu, s1, off);
            s2 += __shfl_xor_sync(0xffffffffu, s2, off);
        }
        if (lane == 0) { red1[0] = s1; red2[0] = s2; }
    }
    __syncthreads();
    float mean = red1[0] * (1.0f / Cc);
    float var  = red2[0] * (1.0f / Cc) - mean * mean;
    float rstd = rsqrtf(var + 1e-5f);

    int c = tid * 4;
    float4 sv = *(const float4*)(s + c);
    float4 bv = *(const float4*)(b + c);
    float4 o;
    o.x = (v.x - mean) * rstd * sv.x + bv.x;
    o.y = (v.y - mean) * rstd * sv.y + bv.y;
    o.z = (v.z - mean) * rstd * sv.z + bv.z;
    o.w = (v.w - mean) * rstd * sv.w + bv.w;
    if (rnd) { o.x = tf32r(o.x); o.y = tf32r(o.y); o.z = tf32r(o.z); o.w = tf32r(o.w); }
    *(float4*)(out + (size_t)row * Cc + c) = o;
}

// ---------------------------------------------------------------------------
// Head
// ---------------------------------------------------------------------------
__global__ void head_kernel(const float* __restrict__ xf,
                            const float* __restrict__ hw,
                            float* __restrict__ out)
{
    int row = blockIdx.x;
    int tid = threadIdx.x;
    float a0 = 0.f, a1 = 0.f, a2 = 0.f;
    const float* xr = xf + (size_t)row * Cc;
    for (int k = tid; k < Cc; k += 128) {
        float xv = xr[k];
        a0 = fmaf(xv, hw[k * 3 + 0], a0);
        a1 = fmaf(xv, hw[k * 3 + 1], a1);
        a2 = fmaf(xv, hw[k * 3 + 2], a2);
    }
    __shared__ float r0[128], r1[128], r2[128];
    r0[tid] = a0; r1[tid] = a1; r2[tid] = a2;
    __syncthreads();
    for (int off = 64; off > 0; off >>= 1) {
        if (tid < off) { r0[tid] += r0[tid+off]; r1[tid] += r1[tid+off]; r2[tid] += r2[tid+off]; }
        __syncthreads();
    }
    if (tid == 0) {
        out[row * 3 + 0] = r0[0];
        out[row * 3 + 1] = r1[0];
        out[row * 3 + 2] = r2[0];
    }
}

// ---------------------------------------------------------------------------
// Launch
// ---------------------------------------------------------------------------
extern "C" void kernel_launch(void* const* d_in, const int* in_sizes, int n_in,
                              void* d_out, int out_size)
{
    const float* seqs    = (const float*)d_in[0];
    const int*   seq_ls  = (const int*)  d_in[1];
    const float* wte_w   = (const float*)d_in[2];
    const float* wte_b   = (const float*)d_in[3];
    const float* wpe     = (const float*)d_in[4];
    const float* ln1_s   = (const float*)d_in[5];
    const float* ln1_b   = (const float*)d_in[6];
    const float* attn_w  = (const float*)d_in[7];
    const float* attn_b  = (const float*)d_in[8];
    const float* attnp_w = (const float*)d_in[9];
    const float* attnp_b = (const float*)d_in[10];
    const float* ln2_s   = (const float*)d_in[11];
    const float* ln2_b   = (const float*)d_in[12];
    const float* fc_w    = (const float*)d_in[13];
    const float* fc_b    = (const float*)d_in[14];
    const float* proj_w  = (const float*)d_in[15];
    const float* proj_b  = (const float*)d_in[16];
    const float* lnf_s   = (const float*)d_in[17];
    const float* lnf_b   = (const float*)d_in[18];
    const float* head_w  = (const float*)d_in[19];
    float* out = (float*)d_out;

    float *x, *h, *qkv, *y, *fc;
    float *wR_attn, *wR_attnp, *wR_fc, *wR_proj;
    cudaGetSymbolAddress((void**)&x,   g_x);
    cudaGetSymbolAddress((void**)&h,   g_h);
    cudaGetSymbolAddress((void**)&qkv, g_qkv);
    cudaGetSymbolAddress((void**)&y,   g_y);
    cudaGetSymbolAddress((void**)&fc,  g_fc);
    cudaGetSymbolAddress((void**)&wR_attn,  g_wR_attn);
    cudaGetSymbolAddress((void**)&wR_attnp, g_wR_attnp);
    cudaGetSymbolAddress((void**)&wR_fc,    g_wR_fc);
    cudaGetSymbolAddress((void**)&wR_proj,  g_wR_proj);

    cudaFuncSetAttribute(gemm_tc<false, false, false>,
                         cudaFuncAttributeMaxDynamicSharedMemorySize, GEMM_SMEM);
    cudaFuncSetAttribute(gemm_tc<true, false, true>,
                         cudaFuncAttributeMaxDynamicSharedMemorySize, GEMM_SMEM);
    cudaFuncSetAttribute(gemm_tc64<false, true, false>,
                         cudaFuncAttributeMaxDynamicSharedMemorySize, GEMM64_SMEM);
    cudaFuncSetAttribute(attn_fa,
                         cudaFuncAttributeMaxDynamicSharedMemorySize, FA_SMEM);

    // One-time tf32 rounding of all weights (same layout, no transpose)
    round_w<<<2048, 256>>>(attn_w,  wR_attn,  (size_t)Ll * Cc * 3 * Cc / 4);
    round_w<<<1024, 256>>>(attnp_w, wR_attnp, (size_t)Ll * Cc * Cc / 4);
    round_w<<<2048, 256>>>(fc_w,    wR_fc,    (size_t)Ll * Cc * 4 * Cc / 4);
    round_w<<<2048, 256>>>(proj_w,  wR_proj,  (size_t)Ll * 4 * Cc * Cc / 4);

    // Embedding
    embed_kernel<<<Mrows, 256>>>(seqs, wte_w, wte_b, wpe, x);

    for (int l = 0; l < Ll; l++) {
        ln_kernel<<<Mrows, 256>>>(x, ln1_s + l * Cc, ln1_b + l * Cc, h, 1);
        // QKV: [2048,1024] @ [1024,3072] — 384 CTAs at 128x128
        gemm_tc<false, false, false><<<dim3(3*Cc/128, Mrows/128), 256, GEMM_SMEM>>>(
            h, wR_attn + (size_t)l * Cc * 3*Cc, attn_b + (size_t)l * 3*Cc,
            nullptr, qkv, 3*Cc, Cc);
        attn_fa<<<dim3(Tt/64, Hh, Bb), 128, FA_SMEM>>>(qkv, seq_ls, y);
        // Attn out-proj + residual: N=1024 — 256 CTAs at 64x128
        gemm_tc64<false, true, false><<<dim3(Cc/128, Mrows/64), 256, GEMM64_SMEM>>>(
            y, wR_attnp + (size_t)l * Cc * Cc, attnp_b + (size_t)l * Cc,
            x, x, Cc, Cc);
        ln_kernel<<<Mrows, 256>>>(x, ln2_s + l * Cc, ln2_b + l * Cc, h, 1);
        // FC + ReLU: [2048,1024] @ [1024,4096] — 512 CTAs at 128x128
        gemm_tc<true, false, true><<<dim3(4*Cc/128, Mrows/128), 256, GEMM_SMEM>>>(
            h, wR_fc + (size_t)l * Cc * 4*Cc, fc_b + (size_t)l * 4*Cc,
            nullptr, fc, 4*Cc, Cc);
        // MLP proj + residual: N=1024 — 256 CTAs at 64x128
        gemm_tc64<false, true, false><<<dim3(Cc/128, Mrows/64), 256, GEMM64_SMEM>>>(
            fc, wR_proj + (size_t)l * 4*Cc * Cc, proj_b + (size_t)l * Cc,
            x, x, Cc, 4*Cc);
    }

    ln_kernel<<<Mrows, 256>>>(x, lnf_s, lnf_b, h, 0);
    head_kernel<<<Mrows, 128>>>(h, head_w, out);
}

// round 11
// speedup vs baseline: 1.2211x; 1.2211x over previous
#include <cuda_runtime.h>
#include <cuda_bf16.h>
#include <math.h>
#include <stdint.h>

// Problem constants
#define Bb 4
#define Tt 512
#define Cc 1024
#define Hh 16
#define Ll 8
#define FSs 64
#define Vv 3
#define Dd 64          // head dim
#define Mrows (Bb*Tt)  // 2048

// ---------------------------------------------------------------------------
// Device-global scratch (no allocations allowed)
// ---------------------------------------------------------------------------
__device__ float g_x  [Mrows * Cc];
__device__ float g_h  [Mrows * Cc];
__device__ float g_qkv[Mrows * 3 * Cc];
__device__ float g_y  [Mrows * Cc];
__device__ float g_fc [Mrows * 4 * Cc];
// transposed + tf32-rounded weights: [L][N][K]
__device__ float g_wT_attn [Ll * 3 * Cc * Cc];
__device__ float g_wT_attnp[Ll * Cc * Cc];
__device__ float g_wT_fc   [Ll * 4 * Cc * Cc];
__device__ float g_wT_proj [Ll * Cc * 4 * Cc];

// ---------------------------------------------------------------------------
// Helpers
// ---------------------------------------------------------------------------
__device__ __forceinline__ unsigned f2tf32(float x) {
    unsigned r;
    asm("cvt.rna.tf32.f32 %0, %1;" : "=r"(r) : "f"(x));
    return r;
}
__device__ __forceinline__ float tf32r(float x) { return __uint_as_float(f2tf32(x)); }

__device__ __forceinline__ uint32_t smem_u32(const void* p) {
    uint32_t a;
    asm("{ .reg .u64 t; cvta.to.shared.u64 t, %1; cvt.u32.u64 %0, t; }" : "=r"(a) : "l"(p));
    return a;
}
__device__ __forceinline__ void cp_async16(uint32_t dst, const void* src) {
    asm volatile("cp.async.cg.shared.global [%0], [%1], 16;" :: "r"(dst), "l"(src));
}
#define CP_COMMIT() asm volatile("cp.async.commit_group;" ::: "memory")
#define CP_WAIT(n)  asm volatile("cp.async.wait_group %0;" :: "n"(n) : "memory")

__device__ __forceinline__ void mma_tf32(float c[4], const unsigned a[4],
                                         unsigned b0, unsigned b1) {
    asm volatile(
        "mma.sync.aligned.m16n8k8.row.col.f32.tf32.tf32.f32 "
        "{%0,%1,%2,%3}, {%4,%5,%6,%7}, {%8,%9}, {%0,%1,%2,%3};"
        : "+f"(c[0]), "+f"(c[1]), "+f"(c[2]), "+f"(c[3])
        : "r"(a[0]), "r"(a[1]), "r"(a[2]), "r"(a[3]), "r"(b0), "r"(b1));
}

__device__ __forceinline__ void ldmx4(unsigned r[4], uint32_t addr) {
    asm volatile("ldmatrix.sync.aligned.m8n8.x4.shared.b16 {%0,%1,%2,%3}, [%4];"
                 : "=r"(r[0]), "=r"(r[1]), "=r"(r[2]), "=r"(r[3]) : "r"(addr));
}

// ---------------------------------------------------------------------------
// Weight transpose + tf32 round: out[l][n][k] = tf32(in[l][k][n])
// grid (K/32, N/32, L), block (32, 8)
// ---------------------------------------------------------------------------
__global__ void transpose_w(const float* __restrict__ in, float* __restrict__ out,
                            int K, int N)
{
    __shared__ float t[32][33];
    size_t base = (size_t)blockIdx.z * K * N;
    int k0 = blockIdx.x * 32, n0 = blockIdx.y * 32;
    #pragma unroll
    for (int i = 0; i < 32; i += 8)
        t[threadIdx.y + i][threadIdx.x] =
            in[base + (size_t)(k0 + threadIdx.y + i) * N + n0 + threadIdx.x];
    __syncthreads();
    #pragma unroll
    for (int i = 0; i < 32; i += 8)
        out[base + (size_t)(n0 + threadIdx.y + i) * K + k0 + threadIdx.x] =
            tf32r(t[threadIdx.x][threadIdx.y + i]);
}

// ---------------------------------------------------------------------------
// TF32 tensor-core GEMM: C[M,N] = A[M,K] @ Bt[N,K]^T + bias (+res)(opt ReLU).
// 128x128 tiles, BK=32, 3-stage cp.async with UNCONDITIONAL commit (tail-safe
// group-count invariant: CP_WAIT(1) always guarantees stage kt landed).
// Both operands k-major in smem (stride 36); fragments via ldmatrix.x4
// (verified lane mapping: bit-identical to scalar-LDS fragment math).
// 256 threads = 8 warps (4m x 2n), warp tile 32x64.
// ---------------------------------------------------------------------------
#define LDK 36
#define STG (128 * LDK)
#define GEMM_SMEM (3 * 2 * STG * 4)

template <bool RELU, bool RES, bool ROUND>
__global__ void __launch_bounds__(256, 2)
gemm_tc(const float* __restrict__ A, const float* __restrict__ Bt,
        const float* __restrict__ bias, const float* __restrict__ res,
        float* __restrict__ C, int N, int K)
{
    extern __shared__ float sm[];
    float* Asm = sm;
    float* Bsm = sm + 3 * STG;

    int tid = threadIdx.x;
    int lane = tid & 31;
    int warp = tid >> 5;
    int blockRow = blockIdx.y * 128;
    int blockCol = blockIdx.x * 128;

    const float* Abase = A  + (size_t)blockRow * K;
    const float* Bbase = Bt + (size_t)blockCol * K;
    int nk = K / 32;

    // Each tile is 128 rows x 32 floats = 1024 x 16B chunks.
    // NOTE: no CP_COMMIT inside — caller commits (possibly empty) groups.
    auto load_stage = [&](int kt, int s) {
        float* as = Asm + s * STG;
        float* bs = Bsm + s * STG;
        #pragma unroll
        for (int i = 0; i < 4; i++) {
            int q = tid + i * 256;
            int r = q >> 3, c = q & 7;
            cp_async16(smem_u32(as + r * LDK + c * 4),
                       Abase + (size_t)r * K + kt * 32 + c * 4);
            cp_async16(smem_u32(bs + r * LDK + c * 4),
                       Bbase + (size_t)r * K + kt * 32 + c * 4);
        }
    };

    load_stage(0, 0); CP_COMMIT();
    load_stage(1, 1); CP_COMMIT();

    // warp layout: 4 (m) x 2 (n); warp tile 32m x 64n
    int m0 = (warp >> 1) * 32;
    int n0 = (warp & 1) * 64;
    int g  = lane >> 2;
    int tg = lane & 3;

    // ldmatrix per-lane address components
    int a_row  = m0 + (lane & 15);                       // + mt*16
    int a_koff = (lane >> 4) * 4;
    int b_row  = n0 + (lane & 7) + ((lane >> 4) << 3);   // + pair*16
    int b_koff = ((lane >> 3) & 1) * 4;

    float acc[2][8][4];
    #pragma unroll
    for (int mt = 0; mt < 2; mt++)
        #pragma unroll
        for (int nt = 0; nt < 8; nt++)
            #pragma unroll
            for (int i = 0; i < 4; i++) acc[mt][nt][i] = 0.f;

    for (int kt = 0; kt < nk; kt++) {
        CP_WAIT(1);          // stage kt resident (2 groups always pending)
        __syncthreads();

        uint32_t as_u = smem_u32(Asm + (kt % 3) * STG);
        uint32_t bs_u = smem_u32(Bsm + (kt % 3) * STG);

        #pragma unroll
        for (int ks = 0; ks < 32; ks += 8) {
            unsigned af[2][4];
            ldmx4(af[0], as_u + ((a_row)      * LDK + ks + a_koff) * 4);
            ldmx4(af[1], as_u + ((a_row + 16) * LDK + ks + a_koff) * 4);

            unsigned bq[8][2];
            #pragma unroll
            for (int p = 0; p < 4; p++) {
                unsigned t4[4];
                ldmx4(t4, bs_u + ((b_row + p * 16) * LDK + ks + b_koff) * 4);
                bq[2*p][0]   = t4[0]; bq[2*p][1]   = t4[1];
                bq[2*p+1][0] = t4[2]; bq[2*p+1][1] = t4[3];
            }

            #pragma unroll
            for (int nt = 0; nt < 8; nt++) {
                mma_tf32(acc[0][nt], af[0], bq[nt][0], bq[nt][1]);
                mma_tf32(acc[1][nt], af[1], bq[nt][0], bq[nt][1]);
            }
        }

        if (kt + 2 < nk) load_stage(kt + 2, (kt + 2) % 3);
        CP_COMMIT();         // unconditional: keeps group-count invariant
    }

    // epilogue
    #pragma unroll
    for (int mt = 0; mt < 2; mt++) {
        #pragma unroll
        for (int nt = 0; nt < 8; nt++) {
            int col = blockCol + n0 + nt * 8 + tg * 2;
            size_t r0 = blockRow + m0 + mt * 16 + g;
            size_t r1 = r0 + 8;
            float b0v = bias[col], b1v = bias[col + 1];
            float2 o0 = make_float2(acc[mt][nt][0] + b0v, acc[mt][nt][1] + b1v);
            float2 o1 = make_float2(acc[mt][nt][2] + b0v, acc[mt][nt][3] + b1v);
            if (RES) {
                float2 rv0 = *(const float2*)(res + r0 * N + col);
                float2 rv1 = *(const float2*)(res + r1 * N + col);
                o0.x += rv0.x; o0.y += rv0.y;
                o1.x += rv1.x; o1.y += rv1.y;
            }
            if (RELU) {
                o0.x = fmaxf(o0.x, 0.f); o0.y = fmaxf(o0.y, 0.f);
                o1.x = fmaxf(o1.x, 0.f); o1.y = fmaxf(o1.y, 0.f);
            }
            if (ROUND) {
                o0.x = tf32r(o0.x); o0.y = tf32r(o0.y);
                o1.x = tf32r(o1.x); o1.y = tf32r(o1.y);
            }
            *(float2*)(C + r0 * N + col) = o0;
            *(float2*)(C + r1 * N + col) = o1;
        }
    }
}

// ---------------------------------------------------------------------------
// Flash attention (tf32 mma) — unchanged from R7/R10 (tail-safe commits).
// ---------------------------------------------------------------------------
#define FLD 68
#define FA_TILE (64 * FLD)
#define FA_SMEM (4 * FA_TILE * 4)

__global__ void __launch_bounds__(128)
attn_fa(const float* __restrict__ qkv,
        const int* __restrict__ seq_ls,
        float* __restrict__ y)
{
    extern __shared__ float fsm[];
    float* Qs = fsm;
    float* Ks = Qs + FA_TILE;
    float* Vs = Ks + FA_TILE;
    float* Ps = Vs + FA_TILE;

    int tid  = threadIdx.x;
    int lane = tid & 31;
    int warp = tid >> 5;
    int g  = lane >> 2;
    int tg = lane & 3;
    int qb = blockIdx.x;
    int h  = blockIdx.y;
    int b  = blockIdx.z;
    int m0w = warp * 16;

    int lv = seq_ls[b];
    int ntiles = (lv + 63) >> 6;

    const float* qkv_b = qkv + (size_t)b * Tt * 3 * Cc;

    #pragma unroll
    for (int i = 0; i < 8; i++) {
        int q = i * 128 + tid;
        int r = q >> 4, c4 = q & 15;
        float4 v = *(const float4*)(qkv_b + (size_t)(qb * 64 + r) * 3 * Cc + h * Dd + c4 * 4);
        v.x = tf32r(v.x * 0.125f); v.y = tf32r(v.y * 0.125f);
        v.z = tf32r(v.z * 0.125f); v.w = tf32r(v.w * 0.125f);
        *(float4*)(Qs + r * FLD + c4 * 4) = v;
    }

    uint32_t Ks_u = smem_u32(Ks);
    uint32_t Vs_u = smem_u32(Vs);
    auto load_k = [&](int kt) {
        #pragma unroll
        for (int i = 0; i < 8; i++) {
            int q = i * 128 + tid;
            int r = q >> 4, c4 = q & 15;
            cp_async16(Ks_u + (r * FLD + c4 * 4) * 4,
                       qkv_b + (size_t)(kt * 64 + r) * 3 * Cc + Cc + h * Dd + c4 * 4);
        }
    };
    auto load_v = [&](int kt) {
        #pragma unroll
        for (int i = 0; i < 8; i++) {
            int q = i * 128 + tid;
            int r = q >> 4, c4 = q & 15;
            cp_async16(Vs_u + (r * FLD + c4 * 4) * 4,
                       qkv_b + (size_t)(kt * 64 + r) * 3 * Cc + 2 * Cc + h * Dd + c4 * 4);
        }
    };

    load_k(0); CP_COMMIT();
    load_v(0); CP_COMMIT();

    float m0 = -INFINITY, m1 = -INFINITY;
    float l0 = 0.f, l1 = 0.f;
    float oacc[8][4];
    #pragma unroll
    for (int nt = 0; nt < 8; nt++)
        #pragma unroll
        for (int i = 0; i < 4; i++) oacc[nt][i] = 0.f;

    for (int kt = 0; kt < ntiles; kt++) {
        int j0 = kt * 64;
        CP_WAIT(1);
        __syncthreads();

        float s[8][4];
        #pragma unroll
        for (int nt = 0; nt < 8; nt++)
            #pragma unroll
            for (int i = 0; i < 4; i++) s[nt][i] = 0.f;

        #pragma unroll
        for (int ks = 0; ks < 8; ks++) {
            unsigned af[4];
            af[0] = __float_as_uint(Qs[(m0w + g) * FLD + ks * 8 + tg]);
            af[1] = __float_as_uint(Qs[(m0w + g + 8) * FLD + ks * 8 + tg]);
            af[2] = __float_as_uint(Qs[(m0w + g) * FLD + ks * 8 + tg + 4]);
            af[3] = __float_as_uint(Qs[(m0w + g + 8) * FLD + ks * 8 + tg + 4]);
            #pragma unroll
            for (int nt = 0; nt < 8; nt++) {
                unsigned b0 = __float_as_uint(Ks[(nt * 8 + g) * FLD + ks * 8 + tg]);
                unsigned b1 = __float_as_uint(Ks[(nt * 8 + g) * FLD + ks * 8 + tg + 4]);
                mma_tf32(s[nt], af, b0, b1);
            }
        }

        __syncthreads();
        if (kt + 1 < ntiles) load_k(kt + 1);
        CP_COMMIT();

        float mx0 = -INFINITY, mx1 = -INFINITY;
        #pragma unroll
        for (int nt = 0; nt < 8; nt++) {
            int j = j0 + nt * 8 + 2 * tg;
            if (j >= lv)     { s[nt][0] = -INFINITY; s[nt][2] = -INFINITY; }
            if (j + 1 >= lv) { s[nt][1] = -INFINITY; s[nt][3] = -INFINITY; }
            mx0 = fmaxf(mx0, fmaxf(s[nt][0], s[nt][1]));
            mx1 = fmaxf(mx1, fmaxf(s[nt][2], s[nt][3]));
        }
        mx0 = fmaxf(mx0, __shfl_xor_sync(0xffffffffu, mx0, 1));
        mx0 = fmaxf(mx0, __shfl_xor_sync(0xffffffffu, mx0, 2));
        mx1 = fmaxf(mx1, __shfl_xor_sync(0xffffffffu, mx1, 1));
        mx1 = fmaxf(mx1, __shfl_xor_sync(0xffffffffu, mx1, 2));

        float mn0 = fmaxf(m0, mx0), mn1 = fmaxf(m1, mx1);
        float corr0 = __expf(m0 - mn0), corr1 = __expf(m1 - mn1);

        float sum0 = 0.f, sum1 = 0.f;
        #pragma unroll
        for (int nt = 0; nt < 8; nt++) {
            float p00 = __expf(s[nt][0] - mn0);
            float p01 = __expf(s[nt][1] - mn0);
            float p10 = __expf(s[nt][2] - mn1);
            float p11 = __expf(s[nt][3] - mn1);
            sum0 += p00 + p01;
            sum1 += p10 + p11;
            int colr = nt * 8 + 2 * tg;
            *(float2*)(Ps + (m0w + g) * FLD + colr) =
                make_float2(tf32r(p00), tf32r(p01));
            *(float2*)(Ps + (m0w + g + 8) * FLD + colr) =
                make_float2(tf32r(p10), tf32r(p11));
        }
        sum0 += __shfl_xor_sync(0xffffffffu, sum0, 1);
        sum0 += __shfl_xor_sync(0xffffffffu, sum0, 2);
        sum1 += __shfl_xor_sync(0xffffffffu, sum1, 1);
        sum1 += __shfl_xor_sync(0xffffffffu, sum1, 2);
        l0 = l0 * corr0 + sum0;
        l1 = l1 * corr1 + sum1;
        m0 = mn0; m1 = mn1;

        #pragma unroll
        for (int nt = 0; nt < 8; nt++) {
            oacc[nt][0] *= corr0; oacc[nt][1] *= corr0;
            oacc[nt][2] *= corr1; oacc[nt][3] *= corr1;
        }

        CP_WAIT(1);
        __syncthreads();

        #pragma unroll
        for (int ks = 0; ks < 8; ks++) {
            unsigned af[4];
            af[0] = __float_as_uint(Ps[(m0w + g) * FLD + ks * 8 + tg]);
            af[1] = __float_as_uint(Ps[(m0w + g + 8) * FLD + ks * 8 + tg]);
            af[2] = __float_as_uint(Ps[(m0w + g) * FLD + ks * 8 + tg + 4]);
            af[3] = __float_as_uint(Ps[(m0w + g + 8) * FLD + ks * 8 + tg + 4]);
            #pragma unroll
            for (int nt = 0; nt < 8; nt++) {
                unsigned b0 = __float_as_uint(Vs[(ks * 8 + tg) * FLD + nt * 8 + g]);
                unsigned b1 = __float_as_uint(Vs[(ks * 8 + tg + 4) * FLD + nt * 8 + g]);
                mma_tf32(oacc[nt], af, b0, b1);
            }
        }

        __syncthreads();
        if (kt + 1 < ntiles) load_v(kt + 1);
        CP_COMMIT();
    }

    float inv0 = 1.0f / l0, inv1 = 1.0f / l1;
    int t0 = qb * 64 + m0w + g;
    #pragma unroll
    for (int nt = 0; nt < 8; nt++) {
        int col = h * Dd + nt * 8 + 2 * tg;
        *(float2*)(y + (size_t)(b * Tt + t0) * Cc + col) =
            make_float2(tf32r(oacc[nt][0] * inv0), tf32r(oacc[nt][1] * inv0));
        *(float2*)(y + (size_t)(b * Tt + t0 + 8) * Cc + col) =
            make_float2(tf32r(oacc[nt][2] * inv1), tf32r(oacc[nt][3] * inv1));
    }
}

// ---------------------------------------------------------------------------
// Embedding
// ---------------------------------------------------------------------------
__global__ void embed_kernel(const float* __restrict__ seqs,
                             const float* __restrict__ wte_w,
                             const float* __restrict__ wte_b,
                             const float* __restrict__ wpe,
                             float* __restrict__ x)
{
    int m = blockIdx.x;
    int t = m % Tt;
    __shared__ float sf[FSs];
    if (threadIdx.x < FSs) sf[threadIdx.x] = seqs[m * FSs + threadIdx.x];
    __syncthreads();

    #pragma unroll
    for (int cc = 0; cc < 4; cc++) {
        int c = threadIdx.x + cc * 256;
        float acc = wte_b[c] + wpe[t * Cc + c];
        #pragma unroll 8
        for (int f = 0; f < FSs; f++)
            acc = fmaf(sf[f], wte_w[f * Cc + c], acc);
        x[m * Cc + c] = acc;
    }
}

// ---------------------------------------------------------------------------
// LayerNorm
// ---------------------------------------------------------------------------
__global__ void ln_kernel(const float* __restrict__ x,
                          const float* __restrict__ s,
                          const float* __restrict__ b,
                          float* __restrict__ out, int rnd)
{
    int row = blockIdx.x;
    int tid = threadIdx.x;
    const float* xr = x + (size_t)row * Cc;

    float4 v = *(const float4*)(xr + tid * 4);
    float sum = v.x + v.y + v.z + v.w;
    float sumsq = v.x*v.x + v.y*v.y + v.z*v.z + v.w*v.w;

    #pragma unroll
    for (int off = 16; off > 0; off >>= 1) {
        sum   += __shfl_xor_sync(0xffffffffu, sum, off);
        sumsq += __shfl_xor_sync(0xffffffffu, sumsq, off);
    }
    __shared__ float red1[8], red2[8];
    int wid = tid >> 5, lane = tid & 31;
    if (lane == 0) { red1[wid] = sum; red2[wid] = sumsq; }
    __syncthreads();
    if (wid == 0) {
        float s1 = red1[lane & 7], s2 = red2[lane & 7];
        #pragma unroll
        for (int off = 4; off > 0; off >>= 1) {
            s1 += __shfl_xor_sync(0xffffffffu, s1, off);
            s2 += __shfl_xor_sync(0xffffffffu, s2, off);
        }
        if (lane == 0) { red1[0] = s1; red2[0] = s2; }
    }
    __syncthreads();
    float mean = red1[0] * (1.0f / Cc);
    float var  = red2[0] * (1.0f / Cc) - mean * mean;
    float rstd = rsqrtf(var + 1e-5f);

    int c = tid * 4;
    float4 sv = *(const float4*)(s + c);
    float4 bv = *(const float4*)(b + c);
    float4 o;
    o.x = (v.x - mean) * rstd * sv.x + bv.x;
    o.y = (v.y - mean) * rstd * sv.y + bv.y;
    o.z = (v.z - mean) * rstd * sv.z + bv.z;
    o.w = (v.w - mean) * rstd * sv.w + bv.w;
    if (rnd) { o.x = tf32r(o.x); o.y = tf32r(o.y); o.z = tf32r(o.z); o.w = tf32r(o.w); }
    *(float4*)(out + (size_t)row * Cc + c) = o;
}

// ---------------------------------------------------------------------------
// Head
// ---------------------------------------------------------------------------
__global__ void head_kernel(const float* __restrict__ xf,
                            const float* __restrict__ hw,
                            float* __restrict__ out)
{
    int row = blockIdx.x;
    int tid = threadIdx.x;
    float a0 = 0.f, a1 = 0.f, a2 = 0.f;
    const float* xr = xf + (size_t)row * Cc;
    for (int k = tid; k < Cc; k += 128) {
        float xv = xr[k];
        a0 = fmaf(xv, hw[k * 3 + 0], a0);
        a1 = fmaf(xv, hw[k * 3 + 1], a1);
        a2 = fmaf(xv, hw[k * 3 + 2], a2);
    }
    __shared__ float r0[128], r1[128], r2[128];
    r0[tid] = a0; r1[tid] = a1; r2[tid] = a2;
    __syncthreads();
    for (int off = 64; off > 0; off >>= 1) {
        if (tid < off) { r0[tid] += r0[tid+off]; r1[tid] += r1[tid+off]; r2[tid] += r2[tid+off]; }
        __syncthreads();
    }
    if (tid == 0) {
        out[row * 3 + 0] = r0[0];
        out[row * 3 + 1] = r1[0];
        out[row * 3 + 2] = r2[0];
    }
}

// ---------------------------------------------------------------------------
// Launch
// ---------------------------------------------------------------------------
extern "C" void kernel_launch(void* const* d_in, const int* in_sizes, int n_in,
                              void* d_out, int out_size)
{
    const float* seqs    = (const float*)d_in[0];
    const int*   seq_ls  = (const int*)  d_in[1];
    const float* wte_w   = (const float*)d_in[2];
    const float* wte_b   = (const float*)d_in[3];
    const float* wpe     = (const float*)d_in[4];
    const float* ln1_s   = (const float*)d_in[5];
    const float* ln1_b   = (const float*)d_in[6];
    const float* attn_w  = (const float*)d_in[7];
    const float* attn_b  = (const float*)d_in[8];
    const float* attnp_w = (const float*)d_in[9];
    const float* attnp_b = (const float*)d_in[10];
    const float* ln2_s   = (const float*)d_in[11];
    const float* ln2_b   = (const float*)d_in[12];
    const float* fc_w    = (const float*)d_in[13];
    const float* fc_b    = (const float*)d_in[14];
    const float* proj_w  = (const float*)d_in[15];
    const float* proj_b  = (const float*)d_in[16];
    const float* lnf_s   = (const float*)d_in[17];
    const float* lnf_b   = (const float*)d_in[18];
    const float* head_w  = (const float*)d_in[19];
    float* out = (float*)d_out;

    float *x, *h, *qkv, *y, *fc;
    float *wT_attn, *wT_attnp, *wT_fc, *wT_proj;
    cudaGetSymbolAddress((void**)&x,   g_x);
    cudaGetSymbolAddress((void**)&h,   g_h);
    cudaGetSymbolAddress((void**)&qkv, g_qkv);
    cudaGetSymbolAddress((void**)&y,   g_y);
    cudaGetSymbolAddress((void**)&fc,  g_fc);
    cudaGetSymbolAddress((void**)&wT_attn,  g_wT_attn);
    cudaGetSymbolAddress((void**)&wT_attnp, g_wT_attnp);
    cudaGetSymbolAddress((void**)&wT_fc,    g_wT_fc);
    cudaGetSymbolAddress((void**)&wT_proj,  g_wT_proj);

    cudaFuncSetAttribute(gemm_tc<false, false, false>,
                         cudaFuncAttributeMaxDynamicSharedMemorySize, GEMM_SMEM);
    cudaFuncSetAttribute(gemm_tc<false, true, false>,
                         cudaFuncAttributeMaxDynamicSharedMemorySize, GEMM_SMEM);
    cudaFuncSetAttribute(gemm_tc<true, false, true>,
                         cudaFuncAttributeMaxDynamicSharedMemorySize, GEMM_SMEM);
    cudaFuncSetAttribute(attn_fa,
                         cudaFuncAttributeMaxDynamicSharedMemorySize, FA_SMEM);

    // One-time transpose + tf32 round of all weights: [L][K][N] -> [L][N][K]
    transpose_w<<<dim3(Cc/32, 3*Cc/32, Ll), dim3(32, 8)>>>(attn_w,  wT_attn,  Cc,   3*Cc);
    transpose_w<<<dim3(Cc/32,   Cc/32, Ll), dim3(32, 8)>>>(attnp_w, wT_attnp, Cc,   Cc);
    transpose_w<<<dim3(Cc/32, 4*Cc/32, Ll), dim3(32, 8)>>>(fc_w,    wT_fc,    Cc,   4*Cc);
    transpose_w<<<dim3(4*Cc/32, Cc/32, Ll), dim3(32, 8)>>>(proj_w,  wT_proj,  4*Cc, Cc);

    // Embedding
    embed_kernel<<<Mrows, 256>>>(seqs, wte_w, wte_b, wpe, x);

    for (int l = 0; l < Ll; l++) {
        ln_kernel<<<Mrows, 256>>>(x, ln1_s + l * Cc, ln1_b + l * Cc, h, 1);
        gemm_tc<false, false, false><<<dim3(3*Cc/128, Mrows/128), 256, GEMM_SMEM>>>(
            h, wT_attn + (size_t)l * 3*Cc * Cc, attn_b + (size_t)l * 3*Cc,
            nullptr, qkv, 3*Cc, Cc);
        attn_fa<<<dim3(Tt/64, Hh, Bb), 128, FA_SMEM>>>(qkv, seq_ls, y);
        gemm_tc<false, true, false><<<dim3(Cc/128, Mrows/128), 256, GEMM_SMEM>>>(
            y, wT_attnp + (size_t)l * Cc * Cc, attnp_b + (size_t)l * Cc,
            x, x, Cc, Cc);
        ln_kernel<<<Mrows, 256>>>(x, ln2_s + l * Cc, ln2_b + l * Cc, h, 1);
        gemm_tc<true, false, true><<<dim3(4*Cc/128, Mrows/128), 256, GEMM_SMEM>>>(
            h, wT_fc + (size_t)l * Cc * 4*Cc, fc_b + (size_t)l * 4*Cc,
            nullptr, fc, 4*Cc, Cc);
        gemm_tc<false, true, false><<<dim3(Cc/128, Mrows/128), 256, GEMM_SMEM>>>(
            fc, wT_proj + (size_t)l * Cc * 4*Cc, proj_b + (size_t)l * Cc,
            x, x, Cc, 4*Cc);
    }

    ln_kernel<<<Mrows, 256>>>(x, lnf_s, lnf_b, h, 0);
    head_kernel<<<Mrows, 128>>>(h, head_w, out);
}